// round 5
// baseline (speedup 1.0000x reference)
#include <cuda_runtime.h>

#define NN   50000
#define NE   1200000
#define NG   64
#define FN   128
#define FE   32
#define HD   64
#define HIDD 128
#define NL   3

typedef unsigned long long ull;

// ---------------- device scratch ----------------
__device__ __align__(16) float g_ea[(size_t)NE * HD];      // edge embeddings fp32, dst-sorted order
__device__ __align__(16) float g_h[NN * HD];               // node state
__device__ __align__(16) float g_xin[NN * HD];             // conv input (gather source)
__device__ int  g_cnt[NN];                                 // in-degree histogram
__device__ int  g_off[NN + 1];                             // CSR offsets
__device__ int  g_cur[NN];                                 // running scatter cursor
__device__ int  g_srcp[NE];                                // src node per sorted slot
__device__ int  g_epos[NE];                                // sorted slot for edge e
__device__ unsigned int g_pool[NG * HD];                   // encoded max-pool
__device__ __align__(16) float g_w1t[NL][HD][HIDD];        // conv_w1^T  [l][k][j]
__device__ __align__(16) float g_w2t[NL][HIDD][HD];        // conv_w2^T  [l][j][o]

__device__ __forceinline__ unsigned fenc(float f) {
    unsigned u = __float_as_uint(f);
    return (u & 0x80000000u) ? ~u : (u | 0x80000000u);
}
__device__ __forceinline__ float fdec(unsigned u) {
    return (u & 0x80000000u) ? __uint_as_float(u & 0x7fffffffu) : __uint_as_float(~u);
}

__device__ __forceinline__ void warp_reduce2(float& s, float& s2) {
#pragma unroll
    for (int o = 16; o > 0; o >>= 1) {
        s  += __shfl_xor_sync(0xffffffffu, s,  o);
        s2 += __shfl_xor_sync(0xffffffffu, s2, o);
    }
}

// ---- packed f32x2 helpers (FFMA2 on sm_103a) ----
__device__ __forceinline__ ull f2pack(float lo, float hi) {
    ull r; asm("mov.b64 %0,{%1,%2};" : "=l"(r) : "f"(lo), "f"(hi)); return r;
}
__device__ __forceinline__ void f2unpack(ull v, float& lo, float& hi) {
    asm("mov.b64 {%0,%1},%2;" : "=f"(lo), "=f"(hi) : "l"(v));
}
__device__ __forceinline__ ull ffma2(ull a, ull b, ull c) {
    ull d; asm("fma.rn.f32x2 %0,%1,%2,%3;" : "=l"(d) : "l"(a), "l"(b), "l"(c)); return d;
}

// ---------------- setup: zero counters + pool ----------------
__global__ void k_zero() {
    int i = blockIdx.x * blockDim.x + threadIdx.x;
    if (i < NN) g_cnt[i] = 0;
    if (i < NG * HD) g_pool[i] = 0u;
}

// ---------------- CSR build ----------------
__global__ void k_hist(const int* __restrict__ dst) {
    int e = blockIdx.x * blockDim.x + threadIdx.x;
    if (e < NE) atomicAdd(&g_cnt[dst[e]], 1);
}

__global__ void k_scan() {
    __shared__ int part[1024];
    int t = threadIdx.x;
    const int per = (NN + 1023) / 1024;   // 49
    int base = t * per;
    int s = 0;
#pragma unroll 4
    for (int i = 0; i < per; i++) {
        int b = base + i;
        if (b < NN) s += g_cnt[b];
    }
    part[t] = s;
    __syncthreads();
    for (int o = 1; o < 1024; o <<= 1) {
        int v = (t >= o) ? part[t - o] : 0;
        __syncthreads();
        part[t] += v;
        __syncthreads();
    }
    int run = part[t] - s;   // exclusive prefix
    for (int i = 0; i < per; i++) {
        int b = base + i;
        if (b < NN) {
            g_off[b] = run;
            g_cur[b] = run;
            run += g_cnt[b];
        }
    }
    if (t == 1023) g_off[NN] = part[1023];
}

__global__ void k_scatter(const int* __restrict__ src, const int* __restrict__ dst) {
    int e = blockIdx.x * blockDim.x + threadIdx.x;
    if (e >= NE) return;
    int d = dst[e];
    int p = atomicAdd(&g_cur[d], 1);
    g_srcp[p] = src[e];
    g_epos[e] = p;
}

// ---------------- weight transposes ----------------
__global__ void k_transpose(const float* __restrict__ cw1, const float* __restrict__ cw2) {
    int i = blockIdx.x * blockDim.x + threadIdx.x;
    if (i < NL * HIDD * HD) {            // cw1: [L][128][64]
        int l = i / (HIDD * HD), r = i % (HIDD * HD);
        int j = r / HD, k = r % HD;
        g_w1t[l][k][j] = cw1[i];
    }
    if (i < NL * HD * HIDD) {            // cw2: [L][64][128]
        int l = i / (HD * HIDD), r = i % (HD * HIDD);
        int o = r / HIDD, j = r % HIDD;
        g_w2t[l][j][o] = cw2[i];
    }
}

// ---------------- node embedding: h = x @ ne_w^T + ne_b ----------------
__global__ void k_node_embed(const float* __restrict__ x,
                             const float* __restrict__ ne_w,
                             const float* __restrict__ ne_b) {
    __shared__ float wst[FN][HD];
    __shared__ float xsh[8][FN];
    for (int idx = threadIdx.x; idx < FN * HD; idx += blockDim.x) {
        int j = idx & (HD - 1), k = idx >> 6;
        wst[k][j] = ne_w[j * FN + k];
    }
    __syncthreads();
    int warp = threadIdx.x >> 5, lane = threadIdx.x & 31;
    int n = blockIdx.x * 8 + warp;
    if (n >= NN) return;
    ((float4*)xsh[warp])[lane] = ((const float4*)x)[(size_t)n * (FN / 4) + lane];
    __syncwarp();
    float acc0 = ne_b[lane], acc1 = ne_b[lane + 32];
#pragma unroll
    for (int k = 0; k < FN; k++) {
        float xk = xsh[warp][k];
        acc0 = fmaf(xk, wst[k][lane], acc0);
        acc1 = fmaf(xk, wst[k][lane + 32], acc1);
    }
    g_h[n * HD + lane]      = acc0;
    g_h[n * HD + lane + 32] = acc1;
}

// ---------------- copy h -> xin (layer-0 gather source; fixes fused-layer race) ----------------
__global__ void k_copy0() {
    int i = blockIdx.x * blockDim.x + threadIdx.x;
    if (i < NN * HD / 4) ((float4*)g_xin)[i] = ((const float4*)g_h)[i];
}

// ---------------- edge MLP (f32x2 math, fp32 scattered store) ----------------
__global__ void __launch_bounds__(128) k_edge_mlp(
        const float* __restrict__ attr,
        const float* __restrict__ w1, const float* __restrict__ b1,
        const float* __restrict__ w2, const float* __restrict__ b2) {
    __shared__ ull w1p[FE][FE / 2];
    __shared__ ull w2p[FE][HD / 2];
    __shared__ ull b1p[FE / 2];
    __shared__ ull b2p[HD / 2];
    for (int i = threadIdx.x; i < FE * FE / 2; i += blockDim.x) {
        int k = i / (FE / 2), j2 = i % (FE / 2);
        w1p[k][j2] = f2pack(w1[(2 * j2) * FE + k], w1[(2 * j2 + 1) * FE + k]);
    }
    for (int i = threadIdx.x; i < FE * HD / 2; i += blockDim.x) {
        int j = i / (HD / 2), i2 = i % (HD / 2);
        w2p[j][i2] = f2pack(w2[(2 * i2) * FE + j], w2[(2 * i2 + 1) * FE + j]);
    }
    if (threadIdx.x < FE / 2) b1p[threadIdx.x] = f2pack(b1[2 * threadIdx.x], b1[2 * threadIdx.x + 1]);
    if (threadIdx.x >= 64 && threadIdx.x < 64 + HD / 2) {
        int i2 = threadIdx.x - 64;
        b2p[i2] = f2pack(b2[2 * i2], b2[2 * i2 + 1]);
    }
    __syncthreads();
    int e = blockIdx.x * blockDim.x + threadIdx.x;
    if (e >= NE) return;

    float av[FE];
    const float4* in4 = (const float4*)(attr + (size_t)e * FE);
#pragma unroll
    for (int k4 = 0; k4 < FE / 4; k4++) {
        float4 v = in4[k4];
        av[k4 * 4 + 0] = v.x; av[k4 * 4 + 1] = v.y;
        av[k4 * 4 + 2] = v.z; av[k4 * 4 + 3] = v.w;
    }

    ull hp[FE / 2];
#pragma unroll
    for (int j2 = 0; j2 < FE / 2; j2++) hp[j2] = b1p[j2];
#pragma unroll
    for (int k = 0; k < FE; k++) {
        ull vkk = f2pack(av[k], av[k]);
#pragma unroll
        for (int j2 = 0; j2 < FE / 2; j2++) hp[j2] = ffma2(vkk, w1p[k][j2], hp[j2]);
    }
    float hidv[FE];
#pragma unroll
    for (int j2 = 0; j2 < FE / 2; j2++) {
        float lo, hi; f2unpack(hp[j2], lo, hi);
        hidv[2 * j2]     = fmaxf(lo, 0.0f);
        hidv[2 * j2 + 1] = fmaxf(hi, 0.0f);
    }

    ull op[HD / 2];
#pragma unroll
    for (int i2 = 0; i2 < HD / 2; i2++) op[i2] = b2p[i2];
#pragma unroll
    for (int j = 0; j < FE; j++) {
        ull hjj = f2pack(hidv[j], hidv[j]);
#pragma unroll
        for (int i2 = 0; i2 < HD / 2; i2++) op[i2] = ffma2(hjj, w2p[j][i2], op[i2]);
    }

    int pos = __ldg(&g_epos[e]);
    ulonglong2* out16 = (ulonglong2*)(g_ea + (size_t)pos * HD);
#pragma unroll
    for (int q = 0; q < HD / 4; q++)
        out16[q] = make_ulonglong2(op[2 * q], op[2 * q + 1]);
}

// ---------------- pre-norm: xin = relu(LN(h)) ----------------
__global__ void k_prep(const float* __restrict__ lng, const float* __restrict__ lnb, int layer) {
    int gid = blockIdx.x * blockDim.x + threadIdx.x;
    int n = gid >> 5, lane = gid & 31;
    if (n >= NN) return;
    float v0 = g_h[n * HD + lane], v1 = g_h[n * HD + lane + 32];
    float s = v0 + v1, s2 = v0 * v0 + v1 * v1;
    warp_reduce2(s, s2);
    float mu = s * (1.0f / HD);
    float var = s2 * (1.0f / HD) - mu * mu;
    float rs = rsqrtf(var + 1e-5f);
    const float* g = lng + layer * HD;
    const float* b = lnb + layer * HD;
    g_xin[n * HD + lane]      = fmaxf((v0 - mu) * rs * g[lane] + b[lane], 0.0f);
    g_xin[n * HD + lane + 32] = fmaxf((v1 - mu) * rs * g[lane + 32] + b[lane + 32], 0.0f);
}

// ---------------- fused layer: edge aggregate (CSR, no atomics) + node MLP ----------------
// Gather source is ALWAYS g_xin (never the g_h output buffer) — no cross-block race.
__global__ void k_layer(int resid, int layer,
                        const float* __restrict__ cb1, const float* __restrict__ cg,
                        const float* __restrict__ cbn, const float* __restrict__ cb2,
                        const float* __restrict__ ct) {
    __shared__ float xs[8][HD];
    __shared__ float vs[8][HIDD];
    int warp = threadIdx.x >> 5, lane = threadIdx.x & 31;
    int n = blockIdx.x * 8 + warp;
    if (n >= NN) return;
    const float* xin = g_xin;
    float t = __ldg(ct + layer);
    int j0 = __ldg(&g_off[n]), j1 = __ldg(&g_off[n + 1]);

    // lane owns features 2*lane, 2*lane+1
    float d0 = 0.0f, d1 = 0.0f, w0 = 0.0f, w1a = 0.0f;
    int j = j0;
    while (j < j1) {
        int chunk = min(32, j1 - j);
        int sv = (lane < chunk) ? __ldg(&g_srcp[j + lane]) : 0;
        for (int kk = 0; kk < chunk; kk++) {
            int s = __shfl_sync(0xffffffffu, sv, kk);
            float2 ef = __ldcs(((const float2*)g_ea) + (size_t)(j + kk) * (HD / 2) + lane);
            float2 xv = ((const float2*)xin)[(size_t)s * (HD / 2) + lane];
            float m0 = fmaxf(xv.x + ef.x, 0.0f) + 1e-7f;
            float m1 = fmaxf(xv.y + ef.y, 0.0f) + 1e-7f;
            float a0 = __expf(m0 * t), a1 = __expf(m1 * t);
            d0 += a0; d1 += a1;
            w0 = fmaf(m0, a0, w0); w1a = fmaf(m1, a1, w1a);
        }
        j += chunk;
    }
    float2 xself = ((const float2*)xin)[(size_t)n * (HD / 2) + lane];
    float o0 = w0  / (d0 + 1e-16f) + xself.x;
    float o1 = w1a / (d1 + 1e-16f) + xself.y;
    ((float2*)xs[warp])[lane] = make_float2(o0, o1);
    __syncwarp();

    // GEMM1: lane owns hidden 4*lane..4*lane+3
    float4 b1v = ((const float4*)(cb1 + layer * HIDD))[lane];
    float4 gv  = ((const float4*)(cg  + layer * HIDD))[lane];
    float4 bv  = ((const float4*)(cbn + layer * HIDD))[lane];
    float2 b2v = ((const float2*)(cb2 + layer * HD))[lane];

    const float4* w1r = (const float4*)g_w1t[layer];
    float4 acc = b1v;
#pragma unroll
    for (int k = 0; k < HD; k++) {
        float xk = xs[warp][k];
        float4 w = w1r[k * (HIDD / 4) + lane];
        acc.x = fmaf(xk, w.x, acc.x);
        acc.y = fmaf(xk, w.y, acc.y);
        acc.z = fmaf(xk, w.z, acc.z);
        acc.w = fmaf(xk, w.w, acc.w);
    }
    float s = acc.x + acc.y + acc.z + acc.w;
    float s2 = acc.x * acc.x + acc.y * acc.y + acc.z * acc.z + acc.w * acc.w;
    warp_reduce2(s, s2);
    float mu = s * (1.0f / HIDD);
    float var = s2 * (1.0f / HIDD) - mu * mu;
    float rs = rsqrtf(var + 1e-5f);
    float4 v;
    v.x = fmaxf((acc.x - mu) * rs * gv.x + bv.x, 0.0f);
    v.y = fmaxf((acc.y - mu) * rs * gv.y + bv.y, 0.0f);
    v.z = fmaxf((acc.z - mu) * rs * gv.z + bv.z, 0.0f);
    v.w = fmaxf((acc.w - mu) * rs * gv.w + bv.w, 0.0f);
    ((float4*)vs[warp])[lane] = v;
    __syncwarp();

    // GEMM2: lane owns outputs 2*lane, 2*lane+1
    const float2* w2r = (const float2*)g_w2t[layer];
    float2 acc2 = b2v;
#pragma unroll
    for (int jj = 0; jj < HIDD; jj++) {
        float vj = vs[warp][jj];
        float2 w = w2r[jj * (HD / 2) + lane];
        acc2.x = fmaf(vj, w.x, acc2.x);
        acc2.y = fmaf(vj, w.y, acc2.y);
    }
    float2* hp = (float2*)(g_h) + (size_t)n * (HD / 2) + lane;
    if (resid) { float2 hv = *hp; acc2.x += hv.x; acc2.y += hv.y; }
    *hp = acc2;
}

// ---------------- final norm + global max pool ----------------
__global__ void k_final_pool(const float* __restrict__ lng, const float* __restrict__ lnb,
                             const int* __restrict__ batch) {
    int gid = blockIdx.x * blockDim.x + threadIdx.x;
    int n = gid >> 5, lane = gid & 31;
    if (n >= NN) return;
    float v0 = g_h[n * HD + lane], v1 = g_h[n * HD + lane + 32];
    float s = v0 + v1, s2 = v0 * v0 + v1 * v1;
    warp_reduce2(s, s2);
    float mu = s * (1.0f / HD);
    float var = s2 * (1.0f / HD) - mu * mu;
    float rs = rsqrtf(var + 1e-5f);
    float z0 = fmaxf((v0 - mu) * rs * lng[lane] + lnb[lane], 0.0f);
    float z1 = fmaxf((v1 - mu) * rs * lng[lane + 32] + lnb[lane + 32], 0.0f);
    int g = __ldg(batch + n);
    atomicMax(&g_pool[g * HD + lane],      fenc(z0));
    atomicMax(&g_pool[g * HD + lane + 32], fenc(z1));
}

// ---------------- readout ----------------
__global__ void k_readout(const float* __restrict__ ro_w, const float* __restrict__ ro_b,
                          float* __restrict__ out) {
    int g = threadIdx.x;
    if (g >= NG) return;
    float acc = ro_b[0];
#pragma unroll
    for (int f = 0; f < HD; f++)
        acc = fmaf(fdec(g_pool[g * HD + f]), ro_w[f], acc);
    out[g] = 1.0f / (1.0f + expf(-acc));
}

extern "C" void kernel_launch(void* const* d_in, const int* in_sizes, int n_in,
                              void* d_out, int out_size) {
    const float* x       = (const float*)d_in[0];
    const float* eattr   = (const float*)d_in[1];
    const float* ne_w    = (const float*)d_in[2];
    const float* ne_b    = (const float*)d_in[3];
    const float* ee_w1   = (const float*)d_in[4];
    const float* ee_b1   = (const float*)d_in[5];
    const float* ee_w2   = (const float*)d_in[6];
    const float* ee_b2   = (const float*)d_in[7];
    const float* conv_w1 = (const float*)d_in[8];
    const float* conv_b1 = (const float*)d_in[9];
    const float* conv_g  = (const float*)d_in[10];
    const float* conv_bn = (const float*)d_in[11];
    const float* conv_w2 = (const float*)d_in[12];
    const float* conv_b2 = (const float*)d_in[13];
    const float* conv_t  = (const float*)d_in[14];
    const float* ln_g    = (const float*)d_in[15];
    const float* ln_b    = (const float*)d_in[16];
    const float* ro_w    = (const float*)d_in[17];
    const float* ro_b    = (const float*)d_in[18];
    const int*   eidx    = (const int*)d_in[19];
    const int*   batch   = (const int*)d_in[20];
    const int* src = eidx;
    const int* dst = eidx + NE;
    float* out = (float*)d_out;

    // CSR build
    k_zero<<<(NN + 255) / 256, 256>>>();
    k_hist<<<(NE + 255) / 256, 256>>>(dst);
    k_scan<<<1, 1024>>>();
    k_scatter<<<(NE + 255) / 256, 256>>>(src, dst);

    k_transpose<<<(NL * HIDD * HD + 255) / 256, 256>>>(conv_w1, conv_w2);
    k_node_embed<<<(NN + 7) / 8, 256>>>(x, ne_w, ne_b);
    k_edge_mlp<<<(NE + 127) / 128, 128>>>(eattr, ee_w1, ee_b1, ee_w2, ee_b2);

    // layer 0: gather from a snapshot of h (k_copy0 breaks the write/read alias)
    k_copy0<<<(NN * HD / 4 + 255) / 256, 256>>>();
    k_layer<<<(NN + 7) / 8, 256>>>(0, 0, conv_b1, conv_g, conv_bn, conv_b2, conv_t);

    // layers 1..2: norm->relu->conv->residual
    for (int l = 1; l < NL; l++) {
        k_prep<<<(NN * 32 + 255) / 256, 256>>>(ln_g, ln_b, l);
        k_layer<<<(NN + 7) / 8, 256>>>(1, l, conv_b1, conv_g, conv_bn, conv_b2, conv_t);
    }

    k_final_pool<<<(NN * 32 + 255) / 256, 256>>>(ln_g, ln_b, batch);
    k_readout<<<1, 64>>>(ro_w, ro_b, out);
}

// round 6
// speedup vs baseline: 1.0633x; 1.0633x over previous
#include <cuda_runtime.h>

#define NN   50000
#define NE   1200000
#define NG   64
#define FN   128
#define FE   32
#define HD   64
#define HIDD 128
#define NL   3

typedef unsigned long long ull;

// ---------------- device scratch ----------------
__device__ __align__(16) float g_ea[(size_t)NE * HD];      // edge embeddings fp32, dst-sorted order
__device__ __align__(16) float g_h[NN * HD];               // node state
__device__ __align__(16) float g_xin[NN * HD];             // conv input (gather source)
__device__ int  g_cnt[NN];                                 // in-degree histogram
__device__ int  g_off[NN + 1];                             // CSR offsets
__device__ int  g_cur[NN];                                 // running scatter cursor
__device__ int  g_srcp[NE];                                // src node per sorted slot
__device__ int  g_epos[NE];                                // sorted slot for edge e
__device__ unsigned int g_pool[NG * HD];                   // encoded max-pool
__device__ __align__(16) float g_w1t[NL][HD][HIDD];        // conv_w1^T  [l][k][j]
__device__ __align__(16) float g_w2t[NL][HIDD][HD];        // conv_w2^T  [l][j][o]

__device__ __forceinline__ unsigned fenc(float f) {
    unsigned u = __float_as_uint(f);
    return (u & 0x80000000u) ? ~u : (u | 0x80000000u);
}
__device__ __forceinline__ float fdec(unsigned u) {
    return (u & 0x80000000u) ? __uint_as_float(u & 0x7fffffffu) : __uint_as_float(~u);
}

__device__ __forceinline__ void warp_reduce2(float& s, float& s2) {
#pragma unroll
    for (int o = 16; o > 0; o >>= 1) {
        s  += __shfl_xor_sync(0xffffffffu, s,  o);
        s2 += __shfl_xor_sync(0xffffffffu, s2, o);
    }
}

// ---- packed f32x2 helpers (FFMA2 on sm_103a) ----
__device__ __forceinline__ ull f2pack(float lo, float hi) {
    ull r; asm("mov.b64 %0,{%1,%2};" : "=l"(r) : "f"(lo), "f"(hi)); return r;
}
__device__ __forceinline__ void f2unpack(ull v, float& lo, float& hi) {
    asm("mov.b64 {%0,%1},%2;" : "=f"(lo), "=f"(hi) : "l"(v));
}
__device__ __forceinline__ ull ffma2(ull a, ull b, ull c) {
    ull d; asm("fma.rn.f32x2 %0,%1,%2,%3;" : "=l"(d) : "l"(a), "l"(b), "l"(c)); return d;
}

// ---------------- setup: zero counters + pool ----------------
__global__ void k_zero() {
    int i = blockIdx.x * blockDim.x + threadIdx.x;
    if (i < NN) g_cnt[i] = 0;
    if (i < NG * HD) g_pool[i] = 0u;
}

// ---------------- CSR build ----------------
__global__ void k_hist(const int* __restrict__ dst) {
    int e = blockIdx.x * blockDim.x + threadIdx.x;
    if (e < NE) atomicAdd(&g_cnt[dst[e]], 1);
}

__global__ void k_scan() {
    __shared__ int part[1024];
    int t = threadIdx.x;
    const int per = (NN + 1023) / 1024;   // 49
    int base = t * per;
    int s = 0;
#pragma unroll 4
    for (int i = 0; i < per; i++) {
        int b = base + i;
        if (b < NN) s += g_cnt[b];
    }
    part[t] = s;
    __syncthreads();
    for (int o = 1; o < 1024; o <<= 1) {
        int v = (t >= o) ? part[t - o] : 0;
        __syncthreads();
        part[t] += v;
        __syncthreads();
    }
    int run = part[t] - s;   // exclusive prefix
    for (int i = 0; i < per; i++) {
        int b = base + i;
        if (b < NN) {
            g_off[b] = run;
            g_cur[b] = run;
            run += g_cnt[b];
        }
    }
    if (t == 1023) g_off[NN] = part[1023];
}

__global__ void k_scatter(const int* __restrict__ src, const int* __restrict__ dst) {
    int e = blockIdx.x * blockDim.x + threadIdx.x;
    if (e >= NE) return;
    int d = dst[e];
    int p = atomicAdd(&g_cur[d], 1);
    g_srcp[p] = src[e];
    g_epos[e] = p;
}

// ---------------- weight transposes ----------------
__global__ void k_transpose(const float* __restrict__ cw1, const float* __restrict__ cw2) {
    int i = blockIdx.x * blockDim.x + threadIdx.x;
    if (i < NL * HIDD * HD) {            // cw1: [L][128][64]
        int l = i / (HIDD * HD), r = i % (HIDD * HD);
        int j = r / HD, k = r % HD;
        g_w1t[l][k][j] = cw1[i];
    }
    if (i < NL * HD * HIDD) {            // cw2: [L][64][128]
        int l = i / (HD * HIDD), r = i % (HD * HIDD);
        int o = r / HIDD, j = r % HIDD;
        g_w2t[l][j][o] = cw2[i];
    }
}

// ---------------- node embedding: h = x @ ne_w^T + ne_b ----------------
__global__ void k_node_embed(const float* __restrict__ x,
                             const float* __restrict__ ne_w,
                             const float* __restrict__ ne_b) {
    __shared__ float wst[FN][HD];
    __shared__ float xsh[8][FN];
    for (int idx = threadIdx.x; idx < FN * HD; idx += blockDim.x) {
        int j = idx & (HD - 1), k = idx >> 6;
        wst[k][j] = ne_w[j * FN + k];
    }
    __syncthreads();
    int warp = threadIdx.x >> 5, lane = threadIdx.x & 31;
    int n = blockIdx.x * 8 + warp;
    if (n >= NN) return;
    ((float4*)xsh[warp])[lane] = ((const float4*)x)[(size_t)n * (FN / 4) + lane];
    __syncwarp();
    float acc0 = ne_b[lane], acc1 = ne_b[lane + 32];
#pragma unroll
    for (int k = 0; k < FN; k++) {
        float xk = xsh[warp][k];
        acc0 = fmaf(xk, wst[k][lane], acc0);
        acc1 = fmaf(xk, wst[k][lane + 32], acc1);
    }
    g_h[n * HD + lane]      = acc0;
    g_h[n * HD + lane + 32] = acc1;
}

// ---------------- copy h -> xin (layer-0 gather source) ----------------
__global__ void k_copy0() {
    int i = blockIdx.x * blockDim.x + threadIdx.x;
    if (i < NN * HD / 4) ((float4*)g_xin)[i] = ((const float4*)g_h)[i];
}

// ---------------- edge MLP (f32x2 math, fp32 scattered store) ----------------
__global__ void __launch_bounds__(128) k_edge_mlp(
        const float* __restrict__ attr,
        const float* __restrict__ w1, const float* __restrict__ b1,
        const float* __restrict__ w2, const float* __restrict__ b2) {
    __shared__ ull w1p[FE][FE / 2];
    __shared__ ull w2p[FE][HD / 2];
    __shared__ ull b1p[FE / 2];
    __shared__ ull b2p[HD / 2];
    for (int i = threadIdx.x; i < FE * FE / 2; i += blockDim.x) {
        int k = i / (FE / 2), j2 = i % (FE / 2);
        w1p[k][j2] = f2pack(w1[(2 * j2) * FE + k], w1[(2 * j2 + 1) * FE + k]);
    }
    for (int i = threadIdx.x; i < FE * HD / 2; i += blockDim.x) {
        int j = i / (HD / 2), i2 = i % (HD / 2);
        w2p[j][i2] = f2pack(w2[(2 * i2) * FE + j], w2[(2 * i2 + 1) * FE + j]);
    }
    if (threadIdx.x < FE / 2) b1p[threadIdx.x] = f2pack(b1[2 * threadIdx.x], b1[2 * threadIdx.x + 1]);
    if (threadIdx.x >= 64 && threadIdx.x < 64 + HD / 2) {
        int i2 = threadIdx.x - 64;
        b2p[i2] = f2pack(b2[2 * i2], b2[2 * i2 + 1]);
    }
    __syncthreads();
    int e = blockIdx.x * blockDim.x + threadIdx.x;
    if (e >= NE) return;

    float av[FE];
    const float4* in4 = (const float4*)(attr + (size_t)e * FE);
#pragma unroll
    for (int k4 = 0; k4 < FE / 4; k4++) {
        float4 v = __ldcs(in4 + k4);
        av[k4 * 4 + 0] = v.x; av[k4 * 4 + 1] = v.y;
        av[k4 * 4 + 2] = v.z; av[k4 * 4 + 3] = v.w;
    }

    ull hp[FE / 2];
#pragma unroll
    for (int j2 = 0; j2 < FE / 2; j2++) hp[j2] = b1p[j2];
#pragma unroll
    for (int k = 0; k < FE; k++) {
        ull vkk = f2pack(av[k], av[k]);
#pragma unroll
        for (int j2 = 0; j2 < FE / 2; j2++) hp[j2] = ffma2(vkk, w1p[k][j2], hp[j2]);
    }
    float hidv[FE];
#pragma unroll
    for (int j2 = 0; j2 < FE / 2; j2++) {
        float lo, hi; f2unpack(hp[j2], lo, hi);
        hidv[2 * j2]     = fmaxf(lo, 0.0f);
        hidv[2 * j2 + 1] = fmaxf(hi, 0.0f);
    }

    ull op[HD / 2];
#pragma unroll
    for (int i2 = 0; i2 < HD / 2; i2++) op[i2] = b2p[i2];
#pragma unroll
    for (int j = 0; j < FE; j++) {
        ull hjj = f2pack(hidv[j], hidv[j]);
#pragma unroll
        for (int i2 = 0; i2 < HD / 2; i2++) op[i2] = ffma2(hjj, w2p[j][i2], op[i2]);
    }

    int pos = __ldg(&g_epos[e]);
    ulonglong2* out16 = (ulonglong2*)(g_ea + (size_t)pos * HD);
#pragma unroll
    for (int q = 0; q < HD / 4; q++)
        out16[q] = make_ulonglong2(op[2 * q], op[2 * q + 1]);
}

// ---------------- pre-norm: xin = relu(LN(h)) ----------------
__global__ void k_prep(const float* __restrict__ lng, const float* __restrict__ lnb, int layer) {
    int gid = blockIdx.x * blockDim.x + threadIdx.x;
    int n = gid >> 5, lane = gid & 31;
    if (n >= NN) return;
    float v0 = g_h[n * HD + lane], v1 = g_h[n * HD + lane + 32];
    float s = v0 + v1, s2 = v0 * v0 + v1 * v1;
    warp_reduce2(s, s2);
    float mu = s * (1.0f / HD);
    float var = s2 * (1.0f / HD) - mu * mu;
    float rs = rsqrtf(var + 1e-5f);
    const float* g = lng + layer * HD;
    const float* b = lnb + layer * HD;
    g_xin[n * HD + lane]      = fmaxf((v0 - mu) * rs * g[lane] + b[lane], 0.0f);
    g_xin[n * HD + lane + 32] = fmaxf((v1 - mu) * rs * g[lane + 32] + b[lane + 32], 0.0f);
}

// ---------------- fused layer: pipelined CSR edge aggregate + node MLP ----------------
__global__ void __launch_bounds__(256) k_layer(
                        int resid, int layer,
                        const float* __restrict__ cb1, const float* __restrict__ cg,
                        const float* __restrict__ cbn, const float* __restrict__ cb2,
                        const float* __restrict__ ct) {
    __shared__ float xs[8][HD];
    __shared__ float vs[8][HIDD];
    int warp = threadIdx.x >> 5, lane = threadIdx.x & 31;
    int n = blockIdx.x * 8 + warp;
    if (n >= NN) return;
    float t = __ldg(ct + layer);
    int j0 = __ldg(&g_off[n]), j1 = __ldg(&g_off[n + 1]);
    int nk = j1 - j0;

    const float2* ea2  = (const float2*)g_ea;
    const float2* xin2 = (const float2*)g_xin;

    // lane owns features 2*lane, 2*lane+1 — 4-wide software pipeline over edges
    float d0 = 0.0f, d1 = 0.0f, w0 = 0.0f, w1a = 0.0f;
    for (int base = 0; base < nk; base += 32) {
        int cn = nk - base; if (cn > 32) cn = 32;
        int sv = (lane < cn) ? __ldg(&g_srcp[j0 + base + lane]) : 0;
        int kk = 0;
        for (; kk + 4 <= cn; kk += 4) {
            int s0 = __shfl_sync(0xffffffffu, sv, kk);
            int s1 = __shfl_sync(0xffffffffu, sv, kk + 1);
            int s2 = __shfl_sync(0xffffffffu, sv, kk + 2);
            int s3 = __shfl_sync(0xffffffffu, sv, kk + 3);
            size_t eb = (size_t)(j0 + base + kk) * (HD / 2) + lane;
            float2 e0 = __ldcs(ea2 + eb);
            float2 e1 = __ldcs(ea2 + eb + (HD / 2));
            float2 e2 = __ldcs(ea2 + eb + 2 * (HD / 2));
            float2 e3 = __ldcs(ea2 + eb + 3 * (HD / 2));
            float2 x0 = __ldg(xin2 + (size_t)s0 * (HD / 2) + lane);
            float2 x1 = __ldg(xin2 + (size_t)s1 * (HD / 2) + lane);
            float2 x2 = __ldg(xin2 + (size_t)s2 * (HD / 2) + lane);
            float2 x3 = __ldg(xin2 + (size_t)s3 * (HD / 2) + lane);
#define AGG_ONE(EV, XV)                                                     \
            {                                                               \
                float m0 = fmaxf(XV.x + EV.x, 0.0f) + 1e-7f;                \
                float m1 = fmaxf(XV.y + EV.y, 0.0f) + 1e-7f;                \
                float a0 = __expf(m0 * t), a1 = __expf(m1 * t);             \
                d0 += a0; d1 += a1;                                         \
                w0 = fmaf(m0, a0, w0); w1a = fmaf(m1, a1, w1a);             \
            }
            AGG_ONE(e0, x0) AGG_ONE(e1, x1) AGG_ONE(e2, x2) AGG_ONE(e3, x3)
        }
        for (; kk < cn; kk++) {
            int s = __shfl_sync(0xffffffffu, sv, kk);
            float2 ev = __ldcs(ea2 + (size_t)(j0 + base + kk) * (HD / 2) + lane);
            float2 xv = __ldg(xin2 + (size_t)s * (HD / 2) + lane);
            AGG_ONE(ev, xv)
        }
#undef AGG_ONE
    }
    float2 xself = xin2[(size_t)n * (HD / 2) + lane];
    float o0 = w0  / (d0 + 1e-16f) + xself.x;
    float o1 = w1a / (d1 + 1e-16f) + xself.y;
    ((float2*)xs[warp])[lane] = make_float2(o0, o1);
    __syncwarp();

    // load biases AFTER aggregation (keeps live ranges short in the edge loop)
    float4 b1v = ((const float4*)(cb1 + layer * HIDD))[lane];
    float4 gv  = ((const float4*)(cg  + layer * HIDD))[lane];
    float4 bv  = ((const float4*)(cbn + layer * HIDD))[lane];
    float2 b2v = ((const float2*)(cb2 + layer * HD))[lane];

    // GEMM1: lane owns hidden 4*lane..4*lane+3
    const float4* w1r = (const float4*)g_w1t[layer];
    float4 acc = b1v;
#pragma unroll
    for (int k = 0; k < HD; k++) {
        float xk = xs[warp][k];
        float4 w = w1r[k * (HIDD / 4) + lane];
        acc.x = fmaf(xk, w.x, acc.x);
        acc.y = fmaf(xk, w.y, acc.y);
        acc.z = fmaf(xk, w.z, acc.z);
        acc.w = fmaf(xk, w.w, acc.w);
    }
    float s = acc.x + acc.y + acc.z + acc.w;
    float s2 = acc.x * acc.x + acc.y * acc.y + acc.z * acc.z + acc.w * acc.w;
    warp_reduce2(s, s2);
    float mu = s * (1.0f / HIDD);
    float var = s2 * (1.0f / HIDD) - mu * mu;
    float rs = rsqrtf(var + 1e-5f);
    float4 v;
    v.x = fmaxf((acc.x - mu) * rs * gv.x + bv.x, 0.0f);
    v.y = fmaxf((acc.y - mu) * rs * gv.y + bv.y, 0.0f);
    v.z = fmaxf((acc.z - mu) * rs * gv.z + bv.z, 0.0f);
    v.w = fmaxf((acc.w - mu) * rs * gv.w + bv.w, 0.0f);
    ((float4*)vs[warp])[lane] = v;
    __syncwarp();

    // GEMM2: lane owns outputs 2*lane, 2*lane+1
    const float2* w2r = (const float2*)g_w2t[layer];
    float2 acc2 = b2v;
#pragma unroll
    for (int jj = 0; jj < HIDD; jj++) {
        float vj = vs[warp][jj];
        float2 w = w2r[jj * (HD / 2) + lane];
        acc2.x = fmaf(vj, w.x, acc2.x);
        acc2.y = fmaf(vj, w.y, acc2.y);
    }
    float2* hp = (float2*)(g_h) + (size_t)n * (HD / 2) + lane;
    if (resid) { float2 hv = *hp; acc2.x += hv.x; acc2.y += hv.y; }
    *hp = acc2;
}

// ---------------- final norm + global max pool ----------------
__global__ void k_final_pool(const float* __restrict__ lng, const float* __restrict__ lnb,
                             const int* __restrict__ batch) {
    int gid = blockIdx.x * blockDim.x + threadIdx.x;
    int n = gid >> 5, lane = gid & 31;
    if (n >= NN) return;
    float v0 = g_h[n * HD + lane], v1 = g_h[n * HD + lane + 32];
    float s = v0 + v1, s2 = v0 * v0 + v1 * v1;
    warp_reduce2(s, s2);
    float mu = s * (1.0f / HD);
    float var = s2 * (1.0f / HD) - mu * mu;
    float rs = rsqrtf(var + 1e-5f);
    float z0 = fmaxf((v0 - mu) * rs * lng[lane] + lnb[lane], 0.0f);
    float z1 = fmaxf((v1 - mu) * rs * lng[lane + 32] + lnb[lane + 32], 0.0f);
    int g = __ldg(batch + n);
    atomicMax(&g_pool[g * HD + lane],      fenc(z0));
    atomicMax(&g_pool[g * HD + lane + 32], fenc(z1));
}

// ---------------- readout ----------------
__global__ void k_readout(const float* __restrict__ ro_w, const float* __restrict__ ro_b,
                          float* __restrict__ out) {
    int g = threadIdx.x;
    if (g >= NG) return;
    float acc = ro_b[0];
#pragma unroll
    for (int f = 0; f < HD; f++)
        acc = fmaf(fdec(g_pool[g * HD + f]), ro_w[f], acc);
    out[g] = 1.0f / (1.0f + expf(-acc));
}

extern "C" void kernel_launch(void* const* d_in, const int* in_sizes, int n_in,
                              void* d_out, int out_size) {
    const float* x       = (const float*)d_in[0];
    const float* eattr   = (const float*)d_in[1];
    const float* ne_w    = (const float*)d_in[2];
    const float* ne_b    = (const float*)d_in[3];
    const float* ee_w1   = (const float*)d_in[4];
    const float* ee_b1   = (const float*)d_in[5];
    const float* ee_w2   = (const float*)d_in[6];
    const float* ee_b2   = (const float*)d_in[7];
    const float* conv_w1 = (const float*)d_in[8];
    const float* conv_b1 = (const float*)d_in[9];
    const float* conv_g  = (const float*)d_in[10];
    const float* conv_bn = (const float*)d_in[11];
    const float* conv_w2 = (const float*)d_in[12];
    const float* conv_b2 = (const float*)d_in[13];
    const float* conv_t  = (const float*)d_in[14];
    const float* ln_g    = (const float*)d_in[15];
    const float* ln_b    = (const float*)d_in[16];
    const float* ro_w    = (const float*)d_in[17];
    const float* ro_b    = (const float*)d_in[18];
    const int*   eidx    = (const int*)d_in[19];
    const int*   batch   = (const int*)d_in[20];
    const int* src = eidx;
    const int* dst = eidx + NE;
    float* out = (float*)d_out;

    // CSR build
    k_zero<<<(NN + 255) / 256, 256>>>();
    k_hist<<<(NE + 255) / 256, 256>>>(dst);
    k_scan<<<1, 1024>>>();
    k_scatter<<<(NE + 255) / 256, 256>>>(src, dst);

    k_transpose<<<(NL * HIDD * HD + 255) / 256, 256>>>(conv_w1, conv_w2);
    k_node_embed<<<(NN + 7) / 8, 256>>>(x, ne_w, ne_b);
    k_edge_mlp<<<(NE + 127) / 128, 128>>>(eattr, ee_w1, ee_b1, ee_w2, ee_b2);

    // layer 0: gather from a snapshot of h
    k_copy0<<<(NN * HD / 4 + 255) / 256, 256>>>();
    k_layer<<<(NN + 7) / 8, 256>>>(0, 0, conv_b1, conv_g, conv_bn, conv_b2, conv_t);

    // layers 1..2: norm->relu->conv->residual
    for (int l = 1; l < NL; l++) {
        k_prep<<<(NN * 32 + 255) / 256, 256>>>(ln_g, ln_b, l);
        k_layer<<<(NN + 7) / 8, 256>>>(1, l, conv_b1, conv_g, conv_bn, conv_b2, conv_t);
    }

    k_final_pool<<<(NN * 32 + 255) / 256, 256>>>(ln_g, ln_b, batch);
    k_readout<<<1, 64>>>(ro_w, ro_b, out);
}